// round 14
// baseline (speedup 1.0000x reference)
#include <cuda_runtime.h>
#include <cuda_fp16.h>
#include <cstdint>

// Problem constants
#define NB      20000
#define S_MAX   25
#define FDIM    256
#define KDIM    512      // 2*FDIM
#define NDIM    256
// Derivation (validated R1/R3/R7/R10): w0 layer is dead code;
// out = relu(concat(self, agg) @ w1.T).
// R2: harness ptxas targets plain sm_103 -> no tcgen05; mma.sync only.
// R8/R10: norm-based error -> single-pass fp16 (rel_err ~3e-4).
// R11: gather needs thread-level occupancy -> boost MLP when residency drops.
// R12: legacy HMMA near its ceiling at ~29us; occupancy not the limiter.
// R13: overlap prep and GEMM in ONE launch via bid-ordered producer blocks
// + spin-waiting consumer tiles (disjoint resources: L2-latency vs tensor).

__device__ __align__(16) __half g_A[(size_t)NB * KDIM];
__device__ __align__(16) __half g_W[(size_t)NDIM * KDIM];

#define NTILE 157
// progress counters (must be 0 at entry and exit of every launch)
__device__ int g_wready[2];             // wconv done per n-half (target 32)
__device__ int g_tileready[NTILE][2];   // gather done per (m-tile, n-half)
__device__ int g_wconsumed[2];          // gemm consumers of W per half

__device__ __forceinline__ uint32_t smem_u32(const void* p) {
    uint32_t a;
    asm("{ .reg .u64 t; cvta.to.shared.u64 t, %1; cvt.u32.u64 %0, t; }"
        : "=r"(a) : "l"(p));
    return a;
}
__device__ __forceinline__ void cpa16(uint32_t dst, const void* src, uint32_t src_bytes) {
    asm volatile("cp.async.cg.shared.global [%0], [%1], 16, %2;"
                 :: "r"(dst), "l"(src), "r"(src_bytes));
}
#define CP_COMMIT() asm volatile("cp.async.commit_group;" ::: "memory")
#define CP_WAIT2()  asm volatile("cp.async.wait_group 2;"  ::: "memory")

#define MMA_F16(d, a, b0, b1)                                                 \
    asm volatile(                                                             \
        "mma.sync.aligned.m16n8k16.row.col.f32.f16.f16.f32 "                  \
        "{%0,%1,%2,%3}, {%4,%5,%6,%7}, {%8,%9}, {%0,%1,%2,%3};"               \
        : "+f"((d)[0]), "+f"((d)[1]), "+f"((d)[2]), "+f"((d)[3])              \
        : "r"((a)[0]), "r"((a)[1]), "r"((a)[2]), "r"((a)[3]), "r"(b0), "r"(b1))

#define LDSM_X4(r, addr)                                                      \
    asm volatile("ldmatrix.sync.aligned.m8n8.x4.shared.b16 {%0,%1,%2,%3}, [%4];" \
        : "=r"((r)[0]), "=r"((r)[1]), "=r"((r)[2]), "=r"((r)[3]) : "r"(addr))

__device__ __forceinline__ void store_h4(__half* __restrict__ dst, float4 v) {
    __half2 h0 = __floats2half2_rn(v.x, v.y);
    __half2 h1 = __floats2half2_rn(v.z, v.w);
    *(uint2*)dst = make_uint2(*(uint32_t*)&h0, *(uint32_t*)&h1);
}
__device__ __forceinline__ void spin_ge(const int* p, int target) {
    while (*(volatile const int*)p < target) __nanosleep(128);
    __threadfence();   // acquire: order spin result before subsequent reads
}
__device__ __forceinline__ void signal(int* p) {
    atomicAdd(p, 1);   // preceded by __threadfence() at call sites (release)
}

// ---------------------------------------------------------------------------
// Block roles by blockIdx.x:
//   [0, 64):            wconv  (w1 -> fp16, 512 float4/block)
//   [64, 64+2500):      gather (8 nodes/block, MLP-8 neighbor loop)
//   [2564, 2564+314):   gemm   (tile t = g>>1, n-half = g&1)
// ---------------------------------------------------------------------------
#define WCV_BLOCKS  64
#define AGG_BLOCKS  2500
#define GEMM_BASE   (WCV_BLOCKS + AGG_BLOCKS)      // 2564
#define GRID_TOTAL  (GEMM_BASE + 2 * NTILE)        // 2878

// GEMM geometry (R12-validated: 512thr, 16 warps 4x4, warp tile 32x32,
// 4-stage cp.async ring, single __syncthreads per kt)
#define BM 128
#define BN 128
#define BK 32
#define NKT (KDIM / BK)            // 16
#define SP  40                      // padded row stride (halves)
#define NSTAGE 4
#define MAT_B   (BM * SP * 2)       // 10240
#define STAGE_B (2 * MAT_B)         // 20480
#define SMEM_BYTES (NSTAGE * STAGE_B)   // 81920

__global__ void __launch_bounds__(512, 2) fused_all_kernel(
    const float* __restrict__ feats,
    const int*   __restrict__ nodes,
    const int*   __restrict__ neighs,
    const int*   __restrict__ val_lens,
    const float* __restrict__ w1,
    float*       __restrict__ out)
{
    const int bid = blockIdx.x;
    const int tid = threadIdx.x;

    // ================= role 1: W conversion =================
    if (bid < WCV_BLOCKS) {
        const int idx = bid * 512 + tid;           // 32768 float4 chunks
        const float4 v = __ldg((const float4*)w1 + idx);
        store_h4(g_W + (size_t)idx * 4, v);
        __threadfence();
        __syncthreads();
        if (tid == 0) signal(&g_wready[bid >> 5]); // 32 blocks per half
        return;
    }

    // ================= role 2: gather + mean =================
    if (bid < GEMM_BASE) {
        const int ablk = bid - WCV_BLOCKS;
        const int slot = tid >> 6;               // 0..7 node slots
        const int t    = tid & 63;               // float4 column chunk
        const int b    = ablk * 8 + slot;        // < 20000 exactly

        const int node = __ldg(nodes + b);
        const int len  = __ldg(val_lens + b);    // >= 1
        const int* nb  = neighs + b * S_MAX;
        const float4* fp = (const float4*)feats; // row stride 64 float4

        const float4 selfv = __ldg(fp + (size_t)node * 64 + t);

        float4 acc = make_float4(0.f, 0.f, 0.f, 0.f);
        int s = 0;
        for (; s + 8 <= len; s += 8) {           // MLP-8 main loop
            int ix[8];
            #pragma unroll
            for (int j = 0; j < 8; ++j) ix[j] = __ldg(nb + s + j);
            float4 v[8];
            #pragma unroll
            for (int j = 0; j < 8; ++j) v[j] = __ldg(fp + (size_t)ix[j] * 64 + t);
            #pragma unroll
            for (int j = 0; j < 8; ++j) {
                acc.x += v[j].x; acc.y += v[j].y;
                acc.z += v[j].z; acc.w += v[j].w;
            }
        }
        for (; s + 4 <= len; s += 4) {
            int ix[4];
            #pragma unroll
            for (int j = 0; j < 4; ++j) ix[j] = __ldg(nb + s + j);
            float4 v[4];
            #pragma unroll
            for (int j = 0; j < 4; ++j) v[j] = __ldg(fp + (size_t)ix[j] * 64 + t);
            #pragma unroll
            for (int j = 0; j < 4; ++j) {
                acc.x += v[j].x; acc.y += v[j].y;
                acc.z += v[j].z; acc.w += v[j].w;
            }
        }
        for (; s < len; ++s) {
            float4 v = __ldg(fp + (size_t)__ldg(nb + s) * 64 + t);
            acc.x += v.x; acc.y += v.y; acc.z += v.z; acc.w += v.w;
        }
        const float fl = (float)len;
        float4 aggv = make_float4(acc.x / fl, acc.y / fl, acc.z / fl, acc.w / fl);

        const size_t rowb = (size_t)b * KDIM;
        store_h4(g_A + rowb + t * 4,        selfv);
        store_h4(g_A + rowb + FDIM + t * 4, aggv);

        __threadfence();
        __syncthreads();
        if (tid == 0) {
            const int tile = ablk >> 4;          // 16 agg blocks per 128 rows
            signal(&g_tileready[tile][0]);
            signal(&g_tileready[tile][1]);
        }
        return;
    }

    // ================= role 3: GEMM tile =================
    extern __shared__ __half sm[];
    const uint32_t sbase = smem_u32(sm);

    const int g  = bid - GEMM_BASE;
    const int tt = g >> 1;
    const int nh = g & 1;
    const int m0 = tt * BM;
    const int n0 = nh * BN;

    if (tid == 0) {
        spin_ge(&g_wready[nh], 32);
        const int target = (tt == NTILE - 1) ? 4 : 16;
        spin_ge(&g_tileready[tt][nh], target);
        g_tileready[tt][nh] = 0;                 // sole consumer resets
        const int old = atomicAdd(&g_wconsumed[nh], 1);
        if (old == NTILE - 1) {                  // last W consumer resets
            g_wready[nh] = 0;
            g_wconsumed[nh] = 0;
        }
    }
    __syncthreads();

    const int lane = tid & 31;
    const int wid  = tid >> 5;
    const int wm   = (wid >> 2) * 32;
    const int wn   = (wid & 3) * 32;
    const int r4   = lane >> 2;
    const int c2   = (lane & 3) * 2;
    const int a_row = (lane & 7) + ((lane >> 3) & 1) * 8;
    const int a_k8  = ((lane >> 4) & 1) * 8;
    const int b_row = (lane & 7) + ((lane >> 4) & 1) * 8;
    const int b_k8  = ((lane >> 3) & 1) * 8;
    const int lrow = tid >> 2;
    const int lc   = tid & 3;

    float acc[2][4][4];
    #pragma unroll
    for (int i = 0; i < 2; ++i)
        #pragma unroll
        for (int j = 0; j < 4; ++j)
            #pragma unroll
            for (int q = 0; q < 4; ++q) acc[i][j][q] = 0.0f;

    auto load_stage = [&](int stage, int kt) {
        const int k0 = kt * BK;
        const uint32_t sbytes = sbase + (uint32_t)stage * STAGE_B;
        const uint32_t soff = (uint32_t)(lrow * SP + lc * 8) * 2;
        const int gm = m0 + lrow;
        const uint32_t abytes = (gm < NB) ? 16u : 0u;
        cpa16(sbytes + soff, g_A + (size_t)gm * KDIM + k0 + lc * 8, abytes);
        cpa16(sbytes + MAT_B + soff,
              g_W + (size_t)(n0 + lrow) * KDIM + k0 + lc * 8, 16u);
    };

    load_stage(0, 0); CP_COMMIT();
    load_stage(1, 1); CP_COMMIT();

    for (int kt = 0; kt < NKT; ++kt) {
        if (kt + 2 < NKT) load_stage((kt + 2) & 3, kt + 2);
        CP_COMMIT();
        CP_WAIT2();
        __syncthreads();

        const uint32_t S  = sbase + (uint32_t)(kt & 3) * STAGE_B;
        const uint32_t aA = S;
        const uint32_t aB = S + MAT_B;

        #pragma unroll
        for (int ks = 0; ks < 2; ++ks) {
            const int kk = ks * 16;
            uint32_t bf[2][4];
            #pragma unroll
            for (int jj = 0; jj < 2; ++jj) {
                const uint32_t boff =
                    (uint32_t)((wn + 16 * jj + b_row) * SP + kk + b_k8) * 2;
                LDSM_X4(bf[jj], aB + boff);
            }
            #pragma unroll
            for (int i = 0; i < 2; ++i) {
                const uint32_t aoff =
                    (uint32_t)((wm + 16 * i + a_row) * SP + kk + a_k8) * 2;
                uint32_t af[4];
                LDSM_X4(af, aA + aoff);
                #pragma unroll
                for (int j = 0; j < 4; ++j) {
                    const int jj = j >> 1, sl = (j & 1) * 2;
                    MMA_F16(acc[i][j], af, bf[jj][sl], bf[jj][sl + 1]);
                }
            }
        }
    }

    // epilogue: fused ReLU, float2 stores
    #pragma unroll
    for (int i = 0; i < 2; ++i) {
        const int gr = m0 + wm + 16 * i + r4;
        #pragma unroll
        for (int half = 0; half < 2; ++half) {
            const int row = gr + 8 * half;
            if (row < NB) {
                #pragma unroll
                for (int j = 0; j < 4; ++j) {
                    const int col = n0 + wn + 8 * j + c2;
                    float2 v;
                    v.x = fmaxf(acc[i][j][2 * half + 0], 0.0f);
                    v.y = fmaxf(acc[i][j][2 * half + 1], 0.0f);
                    *(float2*)&out[(size_t)row * NDIM + col] = v;
                }
            }
        }
    }
}

// ---------------------------------------------------------------------------
// inputs: 0 feats f32, 1 nodes i32, 2 samp_neighs i32, 3 val_lens i32,
// 4 w0 (dead), 5 w1 f32.  output: [20000,256] f32.
// ---------------------------------------------------------------------------
extern "C" void kernel_launch(void* const* d_in, const int* in_sizes, int n_in,
                              void* d_out, int out_size)
{
    const float* feats    = (const float*)d_in[0];
    const int*   nodes    = (const int*)  d_in[1];
    const int*   neighs   = (const int*)  d_in[2];
    const int*   val_lens = (const int*)  d_in[3];
    const float* w1       = (const float*)d_in[5];
    float*       out      = (float*)d_out;

    cudaFuncSetAttribute(fused_all_kernel,
                         cudaFuncAttributeMaxDynamicSharedMemorySize, SMEM_BYTES);
    fused_all_kernel<<<GRID_TOTAL, 512, SMEM_BYTES>>>(feats, nodes, neighs,
                                                      val_lens, w1, out);
}

// round 16
// speedup vs baseline: 1.1127x; 1.1127x over previous
#include <cuda_runtime.h>
#include <cuda_fp16.h>
#include <cstdint>

// Problem constants
#define NB      20000
#define S_MAX   25
#define FDIM    256
#define KDIM    512      // 2*FDIM
#define NDIM    256
// Derivation (validated R1/R3/R7/R10): w0 layer is dead code;
// out = relu(concat(self, agg) @ w1.T).
// R2: harness ptxas targets plain sm_103 -> no tcgen05; mma.sync only.
// R8/R10: norm-based error -> single-pass fp16 (rel_err ~3e-4).
// R11/R14: gather is latency-bound; any config that caps its residency
// (big smem, low blocks/SM, shared launch with GEMM) loses. Keep prep as a
// standalone 256-thread high-occupancy kernel.
// R12: GEMM occupancy not the limiter; bubbles + L2 traffic are.
// R15: BN=256 -> A read once (L2 halved), 157 CTAs = exactly one wave.

__device__ __align__(16) __half g_A[(size_t)NB * KDIM];
__device__ __align__(16) __half g_W[(size_t)NDIM * KDIM];

__device__ __forceinline__ uint32_t smem_u32(const void* p) {
    uint32_t a;
    asm("{ .reg .u64 t; cvta.to.shared.u64 t, %1; cvt.u32.u64 %0, t; }"
        : "=r"(a) : "l"(p));
    return a;
}
__device__ __forceinline__ void cpa16(uint32_t dst, const void* src, uint32_t src_bytes) {
    asm volatile("cp.async.cg.shared.global [%0], [%1], 16, %2;"
                 :: "r"(dst), "l"(src), "r"(src_bytes));
}
#define CP_COMMIT() asm volatile("cp.async.commit_group;" ::: "memory")
#define CP_WAIT2()  asm volatile("cp.async.wait_group 2;"  ::: "memory")

#define MMA_F16(d, a, b0, b1)                                                 \
    asm volatile(                                                             \
        "mma.sync.aligned.m16n8k16.row.col.f32.f16.f16.f32 "                  \
        "{%0,%1,%2,%3}, {%4,%5,%6,%7}, {%8,%9}, {%0,%1,%2,%3};"               \
        : "+f"((d)[0]), "+f"((d)[1]), "+f"((d)[2]), "+f"((d)[3])              \
        : "r"((a)[0]), "r"((a)[1]), "r"((a)[2]), "r"((a)[3]), "r"(b0), "r"(b1))

#define LDSM_X4(r, addr)                                                      \
    asm volatile("ldmatrix.sync.aligned.m8n8.x4.shared.b16 {%0,%1,%2,%3}, [%4];" \
        : "=r"((r)[0]), "=r"((r)[1]), "=r"((r)[2]), "=r"((r)[3]) : "r"(addr))

__device__ __forceinline__ void store_h4(__half* __restrict__ dst, float4 v) {
    __half2 h0 = __floats2half2_rn(v.x, v.y);
    __half2 h1 = __floats2half2_rn(v.z, v.w);
    *(uint2*)dst = make_uint2(*(uint32_t*)&h0, *(uint32_t*)&h1);
}

// ---------------------------------------------------------------------------
// Kernel P (prep): blocks [0, NB/4): gather self + ragged mean -> fp16 rows
// of combined. blocks [NB/4, NB/4+128): convert w1 -> fp16.
// (Unchanged from R10/R12 — measured ~31us, near the L2 gather floor.)
// ---------------------------------------------------------------------------
#define AGG_BLOCKS (NB / 4)      // 5000
#define WCV_BLOCKS 128

__global__ void __launch_bounds__(256) prep_kernel(
    const float* __restrict__ feats,
    const int*   __restrict__ nodes,
    const int*   __restrict__ neighs,
    const int*   __restrict__ val_lens,
    const float* __restrict__ w1)
{
    const int blk = blockIdx.x;

    if (blk >= AGG_BLOCKS) {
        const int idx = (blk - AGG_BLOCKS) * 256 + threadIdx.x;
        const float4 v = __ldg((const float4*)w1 + idx);
        store_h4(g_W + (size_t)idx * 4, v);
        return;
    }

    const int g = threadIdx.x >> 6;          // node slot 0..3
    const int t = threadIdx.x & 63;          // float4 column chunk
    const int b = blk * 4 + g;               // NB % 4 == 0

    const int node = __ldg(nodes + b);
    const int len  = __ldg(val_lens + b);    // >= 1
    const int* nb  = neighs + b * S_MAX;

    const float4* fp = (const float4*)feats; // row stride 64 float4

    const float4 selfv = __ldg(fp + (size_t)node * 64 + t);

    float4 acc = make_float4(0.f, 0.f, 0.f, 0.f);
    int s = 0;
    for (; s + 4 <= len; s += 4) {
        const int i0 = __ldg(nb + s + 0);
        const int i1 = __ldg(nb + s + 1);
        const int i2 = __ldg(nb + s + 2);
        const int i3 = __ldg(nb + s + 3);
        float4 v0 = __ldg(fp + (size_t)i0 * 64 + t);
        float4 v1 = __ldg(fp + (size_t)i1 * 64 + t);
        float4 v2 = __ldg(fp + (size_t)i2 * 64 + t);
        float4 v3 = __ldg(fp + (size_t)i3 * 64 + t);
        acc.x += (v0.x + v1.x) + (v2.x + v3.x);
        acc.y += (v0.y + v1.y) + (v2.y + v3.y);
        acc.z += (v0.z + v1.z) + (v2.z + v3.z);
        acc.w += (v0.w + v1.w) + (v2.w + v3.w);
    }
    for (; s < len; ++s) {
        const int i = __ldg(nb + s);
        float4 v = __ldg(fp + (size_t)i * 64 + t);
        acc.x += v.x; acc.y += v.y; acc.z += v.z; acc.w += v.w;
    }
    const float fl = (float)len;
    float4 aggv = make_float4(acc.x / fl, acc.y / fl, acc.z / fl, acc.w / fl);

    const size_t rowb = (size_t)b * KDIM;
    store_h4(g_A + rowb + t * 4,        selfv);
    store_h4(g_A + rowb + FDIM + t * 4, aggv);
}

// ---------------------------------------------------------------------------
// Kernel B: C = relu(A @ W^T), mma.sync fp16.
// 512 threads / 16 warps (4x4), CTA tile 128x256x32, warp tile 32x64.
// 157 CTAs = one wave. 4-stage cp.async ring, prefetch distance 2, single
// __syncthreads per kt (write (kt+2)&3 vs laggard readers (kt-1)&3: distance
// 3 mod 4, race-free). SP=40 padded stride keeps ldmatrix conflict-free.
// ---------------------------------------------------------------------------
#define BM 128
#define BN 256
#define BK 32
#define NKT (KDIM / BK)            // 16
#define SP  40                      // padded row stride (halves)
#define NSTAGE 4
#define A_B     (BM * SP * 2)       // 10240 bytes
#define W_B     (BN * SP * 2)       // 20480 bytes
#define STAGE_B (A_B + W_B)         // 30720
#define SMEM_BYTES (NSTAGE * STAGE_B)   // 122880

__global__ void __launch_bounds__(512, 1) gemm_mma_kernel(float* __restrict__ out)
{
    extern __shared__ __half sm[];
    const uint32_t sbase = smem_u32(sm);

    const int tid  = threadIdx.x;
    const int lane = tid & 31;
    const int wid  = tid >> 5;          // 0..15
    const int m0   = blockIdx.x * BM;
    const int wm   = (wid >> 2) * 32;   // warp M offset (4 groups x 32 = 128)
    const int wn   = (wid & 3) * 64;    // warp N offset (4 groups x 64 = 256)
    const int r4   = lane >> 2;
    const int c2   = (lane & 3) * 2;

    // ldmatrix lane->row/k mapping (validated R7/R10/R12)
    const int a_row = (lane & 7) + ((lane >> 3) & 1) * 8;
    const int a_k8  = ((lane >> 4) & 1) * 8;
    const int b_row = (lane & 7) + ((lane >> 4) & 1) * 8;
    const int b_k8  = ((lane >> 3) & 1) * 8;

    // loader mapping
    const int lrow = tid >> 2;          // 0..127
    const int lc   = tid & 3;           // 16B sub-chunk

    float acc[2][8][4];
    #pragma unroll
    for (int i = 0; i < 2; ++i)
        #pragma unroll
        for (int j = 0; j < 8; ++j)
            #pragma unroll
            for (int q = 0; q < 4; ++q) acc[i][j][q] = 0.0f;

    auto load_stage = [&](int stage, int kt) {
        const int k0 = kt * BK;
        const uint32_t sbytes = sbase + (uint32_t)stage * STAGE_B;
        // A: 128 rows x 4 chunks = 512 chunks (1/thread)
        {
            const uint32_t soff = (uint32_t)(lrow * SP + lc * 8) * 2;
            const int gm = m0 + lrow;
            const uint32_t abytes = (gm < NB) ? 16u : 0u;
            cpa16(sbytes + soff, g_A + (size_t)gm * KDIM + k0 + lc * 8, abytes);
        }
        // W: 256 rows x 4 chunks = 1024 chunks (2/thread)
        #pragma unroll
        for (int h = 0; h < 2; ++h) {
            const int chunk = tid + h * 512;
            const int row = chunk >> 2;          // 0..255
            const int c   = chunk & 3;
            cpa16(sbytes + A_B + (uint32_t)(row * SP + c * 8) * 2,
                  g_W + (size_t)row * KDIM + k0 + c * 8, 16u);
        }
    };

    load_stage(0, 0); CP_COMMIT();
    load_stage(1, 1); CP_COMMIT();

    for (int kt = 0; kt < NKT; ++kt) {
        if (kt + 2 < NKT) load_stage((kt + 2) & 3, kt + 2);
        CP_COMMIT();
        CP_WAIT2();            // stage kt group complete
        __syncthreads();

        const uint32_t S  = sbase + (uint32_t)(kt & 3) * STAGE_B;
        const uint32_t aA = S;
        const uint32_t aB = S + A_B;

        #pragma unroll
        for (int ks = 0; ks < 2; ++ks) {
            const int kk = ks * 16;
            uint32_t bf[4][4];
            #pragma unroll
            for (int jj = 0; jj < 4; ++jj) {
                const uint32_t boff =
                    (uint32_t)((wn + 16 * jj + b_row) * SP + kk + b_k8) * 2;
                LDSM_X4(bf[jj], aB + boff);
            }
            #pragma unroll
            for (int i = 0; i < 2; ++i) {
                const uint32_t aoff =
                    (uint32_t)((wm + 16 * i + a_row) * SP + kk + a_k8) * 2;
                uint32_t af[4];
                LDSM_X4(af, aA + aoff);
                #pragma unroll
                for (int j = 0; j < 8; ++j) {
                    const int jj = j >> 1, sl = (j & 1) * 2;
                    MMA_F16(acc[i][j], af, bf[jj][sl], bf[jj][sl + 1]);
                }
            }
        }
    }

    // epilogue: fused ReLU, float2 stores
    #pragma unroll
    for (int i = 0; i < 2; ++i) {
        const int gr = m0 + wm + 16 * i + r4;
        #pragma unroll
        for (int half = 0; half < 2; ++half) {
            const int row = gr + 8 * half;
            if (row < NB) {
                #pragma unroll
                for (int j = 0; j < 8; ++j) {
                    const int col = wn + 8 * j + c2;
                    float2 v;
                    v.x = fmaxf(acc[i][j][2 * half + 0], 0.0f);
                    v.y = fmaxf(acc[i][j][2 * half + 1], 0.0f);
                    *(float2*)&out[(size_t)row * NDIM + col] = v;
                }
            }
        }
    }
}

// ---------------------------------------------------------------------------
// inputs: 0 feats f32, 1 nodes i32, 2 samp_neighs i32, 3 val_lens i32,
// 4 w0 (dead), 5 w1 f32.  output: [20000,256] f32.
// ---------------------------------------------------------------------------
extern "C" void kernel_launch(void* const* d_in, const int* in_sizes, int n_in,
                              void* d_out, int out_size)
{
    const float* feats    = (const float*)d_in[0];
    const int*   nodes    = (const int*)  d_in[1];
    const int*   neighs   = (const int*)  d_in[2];
    const int*   val_lens = (const int*)  d_in[3];
    const float* w1       = (const float*)d_in[5];
    float*       out      = (float*)d_out;

    prep_kernel<<<AGG_BLOCKS + WCV_BLOCKS, 256>>>(feats, nodes, neighs,
                                                  val_lens, w1);

    cudaFuncSetAttribute(gemm_mma_kernel,
                         cudaFuncAttributeMaxDynamicSharedMemorySize, SMEM_BYTES);
    gemm_mma_kernel<<<(NB + BM - 1) / BM, 512, SMEM_BYTES>>>(out);
}